// round 12
// baseline (speedup 1.0000x reference)
#include <cuda_runtime.h>
#include <cuda_bf16.h>

#define T_STEPS  2048
#define BATCH    4096
#define INSZ     8
#define HID      20
#define G4       80
#define GROUPS   3       // thread groups per CTA
#define NGE      6       // batch elems per CTA (2 per thread group)
#define NTHREADS 64      // 2 warps; 60 active lanes
#define ROWW     24      // padded smem row (floats): h[0:20], pad

__device__ __forceinline__ float sigmoid_f(float v) {
    return __fdividef(1.0f, 1.0f + __expf(-v));
}
__device__ __forceinline__ float tanh_f(float v) {
    return __fdividef(2.0f, 1.0f + __expf(-2.0f * v)) - 1.0f;
}

__global__ void __launch_bounds__(NTHREADS, 5)
lstm_kernel(const float* __restrict__ x,    // [T, B, 8]
            const float* __restrict__ Wih,  // [8, 80]
            const float* __restrict__ bih,  // [80]
            const float* __restrict__ Whh,  // [20, 80]
            const float* __restrict__ bhh,  // [80]
            const float* __restrict__ hx0,  // [1, 20]
            const float* __restrict__ cx0,  // [1, 20]
            float* __restrict__ out)        // [B, 20]
{
    __shared__ __align__(16) float sv[2][NGE][ROWW];

    const int tid = threadIdx.x;
    const bool active = (tid < GROUPS * HID);   // 60 of 64
    const int tc  = active ? tid : 0;
    const int g   = tc / HID;             // 0..2
    const int j   = tc % HID;             // 0..19
    const int b0  = blockIdx.x * NGE + g;
    const int b1  = b0 + GROUPS;
    const bool ok0 = active && (b0 < BATCH);
    const bool ok1 = active && (b1 < BATCH);
    const int cb0 = (b0 < BATCH) ? b0 : 0;
    const int cb1 = (b1 < BATCH) ? b1 : 0;

    // ---- recurrent weights (80 regs) + input weights (32 regs) for unit j ----
    float wh[HID][4];
#pragma unroll
    for (int k = 0; k < HID; k++)
#pragma unroll
        for (int q = 0; q < 4; q++)
            wh[k][q] = __ldg(&Whh[k * G4 + q * HID + j]);
    float wx[INSZ][4];
#pragma unroll
    for (int k = 0; k < INSZ; k++)
#pragma unroll
        for (int q = 0; q < 4; q++)
            wx[k][q] = __ldg(&Wih[k * G4 + q * HID + j]);

    float bias[4];
#pragma unroll
    for (int q = 0; q < 4; q++)
        bias[q] = __ldg(&bih[q * HID + j]) + __ldg(&bhh[q * HID + j]);

    float h0 = hx0[j], c0 = cx0[j];
    float h1 = h0,     c1 = c0;

    const float4* x4 = reinterpret_cast<const float4*>(x);
    // float4 index for (t, b, half): (t*BATCH + b)*2 + half

    // ---- prologue ----
    // xacc = bias + x_0·W_ih  (x_0 loaded and consumed immediately; one-time stall)
    float xacc0[4], xacc1[4];
    {
        const float4 a0 = x4[(0 * BATCH + cb0) * 2 + 0];
        const float4 a1 = x4[(0 * BATCH + cb0) * 2 + 1];
        const float4 e0 = x4[(0 * BATCH + cb1) * 2 + 0];
        const float4 e1 = x4[(0 * BATCH + cb1) * 2 + 1];
        const float xs0[8] = {a0.x, a0.y, a0.z, a0.w, a1.x, a1.y, a1.z, a1.w};
        const float xs1[8] = {e0.x, e0.y, e0.z, e0.w, e1.x, e1.y, e1.z, e1.w};
#pragma unroll
        for (int q = 0; q < 4; q++) { xacc0[q] = bias[q]; xacc1[q] = bias[q]; }
#pragma unroll
        for (int k = 0; k < INSZ; k++)
#pragma unroll
            for (int q = 0; q < 4; q++) {
                xacc0[q] = fmaf(xs0[k], wx[k][q], xacc0[q]);
                xacc1[q] = fmaf(xs1[k], wx[k][q], xacc1[q]);
            }
    }
    // xn = x_1, resident in registers (consumed at END of step 0 → ~1 step cover)
    float4 xn0a = x4[(1 * BATCH + cb0) * 2 + 0];
    float4 xn0b = x4[(1 * BATCH + cb0) * 2 + 1];
    float4 xn1a = x4[(1 * BATCH + cb1) * 2 + 0];
    float4 xn1b = x4[(1 * BATCH + cb1) * 2 + 1];

    if (active) {
        sv[0][g][j]          = h0;
        sv[0][g + GROUPS][j] = h1;
    }
    __syncthreads();

    int cur = 0;
#pragma unroll 2
    for (int t = 0; t < T_STEPS - 1; t++) {
        const int nxt = cur ^ 1;

        // ---- issue x loads for step t+2 (consumed end of step t+1: ~2 steps of cover) ----
        const int tp = (t + 2 < T_STEPS) ? (t + 2) : (T_STEPS - 1);
        const float4 xp0a = x4[((size_t)tp * BATCH + cb0) * 2 + 0];
        const float4 xp0b = x4[((size_t)tp * BATCH + cb0) * 2 + 1];
        const float4 xp1a = x4[((size_t)tp * BATCH + cb1) * 2 + 0];
        const float4 xp1b = x4[((size_t)tp * BATCH + cb1) * 2 + 1];

        const float4* r0 = reinterpret_cast<const float4*>(sv[cur][g]);
        const float4* r1 = reinterpret_cast<const float4*>(sv[cur][g + GROUPS]);

        // ---- elem 0 gates ----
        float a00 = xacc0[0], a01 = xacc0[1], a02 = xacc0[2], a03 = xacc0[3];
#pragma unroll
        for (int kc = 0; kc < HID / 4; kc++) {
            const float4 u = r0[kc];
            const int k = kc * 4;
            const float ua[4] = {u.x, u.y, u.z, u.w};
#pragma unroll
            for (int s = 0; s < 4; s++) {
                a00 = fmaf(ua[s], wh[k + s][0], a00);
                a01 = fmaf(ua[s], wh[k + s][1], a01);
                a02 = fmaf(ua[s], wh[k + s][2], a02);
                a03 = fmaf(ua[s], wh[k + s][3], a03);
            }
        }
        // elem 0 activations launch early (MUFU overlaps elem 1's FMA issue)
        const float ii0 = sigmoid_f(a00);
        const float ff0 = sigmoid_f(a01);
        const float gg0 = tanh_f(a02);
        const float oo0 = sigmoid_f(a03);

        // ---- elem 1 gates ----
        float a10 = xacc1[0], a11 = xacc1[1], a12 = xacc1[2], a13 = xacc1[3];
#pragma unroll
        for (int kc = 0; kc < HID / 4; kc++) {
            const float4 v = r1[kc];
            const int k = kc * 4;
            const float va[4] = {v.x, v.y, v.z, v.w};
#pragma unroll
            for (int s = 0; s < 4; s++) {
                a10 = fmaf(va[s], wh[k + s][0], a10);
                a11 = fmaf(va[s], wh[k + s][1], a11);
                a12 = fmaf(va[s], wh[k + s][2], a12);
                a13 = fmaf(va[s], wh[k + s][3], a13);
            }
        }
        const float ii1 = sigmoid_f(a10);
        const float ff1 = sigmoid_f(a11);
        const float gg1 = tanh_f(a12);
        const float oo1 = sigmoid_f(a13);

        // ---- x-projection for step t+1 using register-resident xn (fills MUFU shadow) ----
        {
            const float xs0[8] = {xn0a.x, xn0a.y, xn0a.z, xn0a.w,
                                  xn0b.x, xn0b.y, xn0b.z, xn0b.w};
            const float xs1[8] = {xn1a.x, xn1a.y, xn1a.z, xn1a.w,
                                  xn1b.x, xn1b.y, xn1b.z, xn1b.w};
#pragma unroll
            for (int q = 0; q < 4; q++) { xacc0[q] = bias[q]; xacc1[q] = bias[q]; }
#pragma unroll
            for (int k = 0; k < INSZ; k++)
#pragma unroll
                for (int q = 0; q < 4; q++) {
                    xacc0[q] = fmaf(xs0[k], wx[k][q], xacc0[q]);
                    xacc1[q] = fmaf(xs1[k], wx[k][q], xacc1[q]);
                }
        }

        // ---- state update ----
        c0 = ff0 * c0 + ii0 * gg0;
        c1 = ff1 * c1 + ii1 * gg1;
        h0 = oo0 * tanh_f(c0);
        h1 = oo1 * tanh_f(c1);

        if (active) {
            sv[nxt][g][j]          = h0;
            sv[nxt][g + GROUPS][j] = h1;
        }
        __syncthreads();

        // rotate the x pipeline
        xn0a = xp0a; xn0b = xp0b;
        xn1a = xp1a; xn1b = xp1b;
        cur = nxt;
    }

    // ---- peeled final step (no prefetch, no x-proj, no STS/BAR) ----
    {
        const float4* r0 = reinterpret_cast<const float4*>(sv[cur][g]);
        const float4* r1 = reinterpret_cast<const float4*>(sv[cur][g + GROUPS]);

        float a00 = xacc0[0], a01 = xacc0[1], a02 = xacc0[2], a03 = xacc0[3];
        float a10 = xacc1[0], a11 = xacc1[1], a12 = xacc1[2], a13 = xacc1[3];
#pragma unroll
        for (int kc = 0; kc < HID / 4; kc++) {
            const float4 u = r0[kc];
            const float4 v = r1[kc];
            const int k = kc * 4;
            const float ua[4] = {u.x, u.y, u.z, u.w};
            const float va[4] = {v.x, v.y, v.z, v.w};
#pragma unroll
            for (int s = 0; s < 4; s++) {
                a00 = fmaf(ua[s], wh[k + s][0], a00);
                a01 = fmaf(ua[s], wh[k + s][1], a01);
                a02 = fmaf(ua[s], wh[k + s][2], a02);
                a03 = fmaf(ua[s], wh[k + s][3], a03);
                a10 = fmaf(va[s], wh[k + s][0], a10);
                a11 = fmaf(va[s], wh[k + s][1], a11);
                a12 = fmaf(va[s], wh[k + s][2], a12);
                a13 = fmaf(va[s], wh[k + s][3], a13);
            }
        }
        const float ii0 = sigmoid_f(a00);
        const float ff0 = sigmoid_f(a01);
        const float gg0 = tanh_f(a02);
        const float oo0 = sigmoid_f(a03);
        const float ii1 = sigmoid_f(a10);
        const float ff1 = sigmoid_f(a11);
        const float gg1 = tanh_f(a12);
        const float oo1 = sigmoid_f(a13);

        c0 = ff0 * c0 + ii0 * gg0;
        c1 = ff1 * c1 + ii1 * gg1;
        h0 = oo0 * tanh_f(c0);
        h1 = oo1 * tanh_f(c1);
    }

    if (ok0) out[b0 * HID + j] = h0;
    if (ok1) out[b1 * HID + j] = h1;
}

extern "C" void kernel_launch(void* const* d_in, const int* in_sizes, int n_in,
                              void* d_out, int out_size) {
    const float* x   = (const float*)d_in[0];
    const float* Wih = (const float*)d_in[1];
    const float* bih = (const float*)d_in[2];
    const float* Whh = (const float*)d_in[3];
    const float* bhh = (const float*)d_in[4];
    const float* hx0 = (const float*)d_in[5];
    const float* cx0 = (const float*)d_in[6];
    float* out = (float*)d_out;

    const int grid = (BATCH + NGE - 1) / NGE;  // 683
    lstm_kernel<<<grid, NTHREADS>>>(x, Wih, bih, Whh, bhh, hx0, cx0, out);
}

// round 13
// speedup vs baseline: 1.1031x; 1.1031x over previous
#include <cuda_runtime.h>
#include <cuda_bf16.h>

#define T_STEPS  2048
#define BATCH    4096
#define INSZ     8
#define HID      20
#define G4       80
#define GROUPS   3       // thread groups per CTA
#define EPT      3       // batch elems per thread
#define NGE      (GROUPS * EPT)   // 9 batch elems per CTA
#define NTHREADS 64      // 2 warps; 60 active lanes
#define ROWW     24      // padded smem row (floats): h[0:20], pad

__device__ __forceinline__ float sigmoid_f(float v) {
    return __fdividef(1.0f, 1.0f + __expf(-v));
}
__device__ __forceinline__ float tanh_f(float v) {
    return __fdividef(2.0f, 1.0f + __expf(-2.0f * v)) - 1.0f;
}

__global__ void __launch_bounds__(NTHREADS, 4)
lstm_kernel(const float* __restrict__ x,    // [T, B, 8]
            const float* __restrict__ Wih,  // [8, 80]
            const float* __restrict__ bih,  // [80]
            const float* __restrict__ Whh,  // [20, 80]
            const float* __restrict__ bhh,  // [80]
            const float* __restrict__ hx0,  // [1, 20]
            const float* __restrict__ cx0,  // [1, 20]
            float* __restrict__ out)        // [B, 20]
{
    __shared__ __align__(16) float sv[2][NGE][ROWW];

    const int tid = threadIdx.x;
    const bool active = (tid < GROUPS * HID);   // 60 of 64
    const int tc  = active ? tid : 0;
    const int g   = tc / HID;             // 0..2
    const int j   = tc % HID;             // 0..19
    int  bidx[EPT];
    bool okk[EPT];
    int  cbb[EPT];
#pragma unroll
    for (int e = 0; e < EPT; e++) {
        bidx[e] = blockIdx.x * NGE + g + e * GROUPS;
        okk[e]  = active && (bidx[e] < BATCH);
        cbb[e]  = (bidx[e] < BATCH) ? bidx[e] : 0;
    }

    // ---- recurrent weights (80 regs) + input weights (32 regs) for unit j ----
    float wh[HID][4];
#pragma unroll
    for (int k = 0; k < HID; k++)
#pragma unroll
        for (int q = 0; q < 4; q++)
            wh[k][q] = __ldg(&Whh[k * G4 + q * HID + j]);
    float wx[INSZ][4];
#pragma unroll
    for (int k = 0; k < INSZ; k++)
#pragma unroll
        for (int q = 0; q < 4; q++)
            wx[k][q] = __ldg(&Wih[k * G4 + q * HID + j]);

    float bias[4];
#pragma unroll
    for (int q = 0; q < 4; q++)
        bias[q] = __ldg(&bih[q * HID + j]) + __ldg(&bhh[q * HID + j]);

    float hh[EPT], cc[EPT];
#pragma unroll
    for (int e = 0; e < EPT; e++) { hh[e] = hx0[j]; cc[e] = cx0[j]; }

    const float4* x4 = reinterpret_cast<const float4*>(x);
    // float4 index for (t, b, half): (t*BATCH + b)*2 + half

    // ---- prologue: xacc = bias + x_0 * W_ih for all elems ----
    float xacc[EPT][4];
#pragma unroll
    for (int e = 0; e < EPT; e++) {
        const float4 a0 = x4[(0 * BATCH + cbb[e]) * 2 + 0];
        const float4 a1 = x4[(0 * BATCH + cbb[e]) * 2 + 1];
        const float xs[8] = {a0.x, a0.y, a0.z, a0.w, a1.x, a1.y, a1.z, a1.w};
#pragma unroll
        for (int q = 0; q < 4; q++) xacc[e][q] = bias[q];
#pragma unroll
        for (int k = 0; k < INSZ; k++)
#pragma unroll
            for (int q = 0; q < 4; q++)
                xacc[e][q] = fmaf(xs[k], wx[k][q], xacc[e][q]);
    }

    if (active) {
#pragma unroll
        for (int e = 0; e < EPT; e++)
            sv[0][g + e * GROUPS][j] = hh[e];
    }
    __syncthreads();

    int cur = 0;
#pragma unroll 2
    for (int t = 0; t < T_STEPS; t++) {
        const int nxt = cur ^ 1;

        // ---- issue x loads for step t+1 early (latency hidden by FMA block) ----
        const int tn = (t + 1 < T_STEPS) ? (t + 1) : t;
        float4 xna[EPT], xnb[EPT];
#pragma unroll
        for (int e = 0; e < EPT; e++) {
            xna[e] = x4[((size_t)tn * BATCH + cbb[e]) * 2 + 0];
            xnb[e] = x4[((size_t)tn * BATCH + cbb[e]) * 2 + 1];
        }

        // ---- gate sums: 12 interleaved accumulator chains ----
        float acc[EPT][4];
#pragma unroll
        for (int e = 0; e < EPT; e++)
#pragma unroll
            for (int q = 0; q < 4; q++)
                acc[e][q] = xacc[e][q];

#pragma unroll
        for (int kc = 0; kc < HID / 4; kc++) {
            float4 u[EPT];
#pragma unroll
            for (int e = 0; e < EPT; e++)
                u[e] = reinterpret_cast<const float4*>(sv[cur][g + e * GROUPS])[kc];
            const int k = kc * 4;
#pragma unroll
            for (int e = 0; e < EPT; e++) {
                const float ua[4] = {u[e].x, u[e].y, u[e].z, u[e].w};
#pragma unroll
                for (int s = 0; s < 4; s++) {
                    acc[e][0] = fmaf(ua[s], wh[k + s][0], acc[e][0]);
                    acc[e][1] = fmaf(ua[s], wh[k + s][1], acc[e][1]);
                    acc[e][2] = fmaf(ua[s], wh[k + s][2], acc[e][2]);
                    acc[e][3] = fmaf(ua[s], wh[k + s][3], acc[e][3]);
                }
            }
        }

        // ---- activations (MUFU-heavy), all elems together ----
        float ii[EPT], ff[EPT], gg[EPT], oo[EPT];
#pragma unroll
        for (int e = 0; e < EPT; e++) {
            ii[e] = sigmoid_f(acc[e][0]);
            ff[e] = sigmoid_f(acc[e][1]);
            gg[e] = tanh_f(acc[e][2]);
            oo[e] = sigmoid_f(acc[e][3]);
        }

        // ---- next step's x-projection: fills the MUFU shadow ----
#pragma unroll
        for (int e = 0; e < EPT; e++) {
            const float xs[8] = {xna[e].x, xna[e].y, xna[e].z, xna[e].w,
                                 xnb[e].x, xnb[e].y, xnb[e].z, xnb[e].w};
#pragma unroll
            for (int q = 0; q < 4; q++) xacc[e][q] = bias[q];
#pragma unroll
            for (int k = 0; k < INSZ; k++)
#pragma unroll
                for (int q = 0; q < 4; q++)
                    xacc[e][q] = fmaf(xs[k], wx[k][q], xacc[e][q]);
        }

        // ---- state update ----
#pragma unroll
        for (int e = 0; e < EPT; e++) {
            cc[e] = ff[e] * cc[e] + ii[e] * gg[e];
            hh[e] = oo[e] * tanh_f(cc[e]);
        }

        if (t + 1 < T_STEPS) {
            if (active) {
#pragma unroll
                for (int e = 0; e < EPT; e++)
                    sv[nxt][g + e * GROUPS][j] = hh[e];
            }
            __syncthreads();
        }
        cur = nxt;
    }

#pragma unroll
    for (int e = 0; e < EPT; e++)
        if (okk[e]) out[bidx[e] * HID + j] = hh[e];
}

extern "C" void kernel_launch(void* const* d_in, const int* in_sizes, int n_in,
                              void* d_out, int out_size) {
    const float* x   = (const float*)d_in[0];
    const float* Wih = (const float*)d_in[1];
    const float* bih = (const float*)d_in[2];
    const float* Whh = (const float*)d_in[3];
    const float* bhh = (const float*)d_in[4];
    const float* hx0 = (const float*)d_in[5];
    const float* cx0 = (const float*)d_in[6];
    float* out = (float*)d_out;

    const int grid = (BATCH + NGE - 1) / NGE;  // 456
    lstm_kernel<<<grid, NTHREADS>>>(x, Wih, bih, Whh, bhh, hx0, cx0, out);
}

// round 14
// speedup vs baseline: 1.2488x; 1.1321x over previous
#include <cuda_runtime.h>
#include <cuda_bf16.h>

#define T_STEPS  2048
#define BATCH    4096
#define INSZ     8
#define HID      20
#define G4       80
#define GROUPS   3       // thread groups per CTA
#define NGE      6       // batch elems per CTA (2 per thread group)
#define NTHREADS 64      // 2 warps; 60 active lanes
#define ROWW     24      // padded smem row (floats): h[0:20], pad

// hardware tanh: 1 MUFU op (vs ex2+rcp chain)
__device__ __forceinline__ float tanh_hw(float v) {
    float r;
    asm("tanh.approx.f32 %0, %1;" : "=f"(r) : "f"(v));
    return r;
}
// sigmoid(v) = 0.5*tanh(0.5v) + 0.5
__device__ __forceinline__ float sigmoid_hw(float v) {
    return fmaf(tanh_hw(0.5f * v), 0.5f, 0.5f);
}

__global__ void __launch_bounds__(NTHREADS)
lstm_kernel(const float* __restrict__ x,    // [T, B, 8]
            const float* __restrict__ Wih,  // [8, 80]
            const float* __restrict__ bih,  // [80]
            const float* __restrict__ Whh,  // [20, 80]
            const float* __restrict__ bhh,  // [80]
            const float* __restrict__ hx0,  // [1, 20]
            const float* __restrict__ cx0,  // [1, 20]
            float* __restrict__ out)        // [B, 20]
{
    __shared__ __align__(16) float sv[2][NGE][ROWW];

    const int tid = threadIdx.x;
    const bool active = (tid < GROUPS * HID);   // 60 of 64
    const int tc  = active ? tid : 0;
    const int g   = tc / HID;             // 0..2
    const int j   = tc % HID;             // 0..19
    const int b0  = blockIdx.x * NGE + g;
    const int b1  = b0 + GROUPS;
    const bool ok0 = active && (b0 < BATCH);
    const bool ok1 = active && (b1 < BATCH);
    const int cb0 = (b0 < BATCH) ? b0 : 0;
    const int cb1 = (b1 < BATCH) ? b1 : 0;

    // ---- recurrent weights (80 regs) + input weights (32 regs) for unit j ----
    float wh[HID][4];
#pragma unroll
    for (int k = 0; k < HID; k++)
#pragma unroll
        for (int q = 0; q < 4; q++)
            wh[k][q] = __ldg(&Whh[k * G4 + q * HID + j]);
    float wx[INSZ][4];
#pragma unroll
    for (int k = 0; k < INSZ; k++)
#pragma unroll
        for (int q = 0; q < 4; q++)
            wx[k][q] = __ldg(&Wih[k * G4 + q * HID + j]);

    float bias[4];
#pragma unroll
    for (int q = 0; q < 4; q++)
        bias[q] = __ldg(&bih[q * HID + j]) + __ldg(&bhh[q * HID + j]);

    float h0 = hx0[j], c0 = cx0[j];
    float h1 = h0,     c1 = c0;

    const float4* x4 = reinterpret_cast<const float4*>(x);
    // float4 index for (t, b, half): (t*BATCH + b)*2 + half

    // ---- prologue: xacc = bias + x_0 * W_ih for both elems ----
    float xacc0[4], xacc1[4];
    {
        const float4 a0 = x4[(0 * BATCH + cb0) * 2 + 0];
        const float4 a1 = x4[(0 * BATCH + cb0) * 2 + 1];
        const float4 b0v = x4[(0 * BATCH + cb1) * 2 + 0];
        const float4 b1v = x4[(0 * BATCH + cb1) * 2 + 1];
        const float xs0[8] = {a0.x, a0.y, a0.z, a0.w, a1.x, a1.y, a1.z, a1.w};
        const float xs1[8] = {b0v.x, b0v.y, b0v.z, b0v.w, b1v.x, b1v.y, b1v.z, b1v.w};
#pragma unroll
        for (int q = 0; q < 4; q++) { xacc0[q] = bias[q]; xacc1[q] = bias[q]; }
#pragma unroll
        for (int k = 0; k < INSZ; k++)
#pragma unroll
            for (int q = 0; q < 4; q++) {
                xacc0[q] = fmaf(xs0[k], wx[k][q], xacc0[q]);
                xacc1[q] = fmaf(xs1[k], wx[k][q], xacc1[q]);
            }
    }

    if (active) {
        sv[0][g][j]          = h0;
        sv[0][g + GROUPS][j] = h1;
    }
    __syncthreads();

    int cur = 0;
#pragma unroll 2
    for (int t = 0; t < T_STEPS; t++) {
        const int nxt = cur ^ 1;

        // ---- issue x loads for step t+1 early (latency hidden by FMA block) ----
        const int tn = (t + 1 < T_STEPS) ? (t + 1) : t;
        const float4 xa0 = x4[((size_t)tn * BATCH + cb0) * 2 + 0];
        const float4 xa1 = x4[((size_t)tn * BATCH + cb0) * 2 + 1];
        const float4 xb0 = x4[((size_t)tn * BATCH + cb1) * 2 + 0];
        const float4 xb1 = x4[((size_t)tn * BATCH + cb1) * 2 + 1];

        // ---- gate sums: start from precomputed x-part, add h·W_hh ----
        float a00 = xacc0[0], a01 = xacc0[1], a02 = xacc0[2], a03 = xacc0[3];
        float a10 = xacc1[0], a11 = xacc1[1], a12 = xacc1[2], a13 = xacc1[3];

        const float4* r0 = reinterpret_cast<const float4*>(sv[cur][g]);
        const float4* r1 = reinterpret_cast<const float4*>(sv[cur][g + GROUPS]);
#pragma unroll
        for (int kc = 0; kc < HID / 4; kc++) {
            const float4 u = r0[kc];
            const float4 v = r1[kc];
            const int k = kc * 4;
            const float ua[4] = {u.x, u.y, u.z, u.w};
            const float va[4] = {v.x, v.y, v.z, v.w};
#pragma unroll
            for (int s = 0; s < 4; s++) {
                a00 = fmaf(ua[s], wh[k + s][0], a00);
                a01 = fmaf(ua[s], wh[k + s][1], a01);
                a02 = fmaf(ua[s], wh[k + s][2], a02);
                a03 = fmaf(ua[s], wh[k + s][3], a03);
                a10 = fmaf(va[s], wh[k + s][0], a10);
                a11 = fmaf(va[s], wh[k + s][1], a11);
                a12 = fmaf(va[s], wh[k + s][2], a12);
                a13 = fmaf(va[s], wh[k + s][3], a13);
            }
        }

        // ---- activations: 1 MUFU.TANH each ----
        const float ii0 = sigmoid_hw(a00);
        const float ff0 = sigmoid_hw(a01);
        const float gg0 = tanh_hw(a02);
        const float oo0 = sigmoid_hw(a03);
        const float ii1 = sigmoid_hw(a10);
        const float ff1 = sigmoid_hw(a11);
        const float gg1 = tanh_hw(a12);
        const float oo1 = sigmoid_hw(a13);

        // ---- next step's x-projection: independent work that fills the MUFU shadow ----
        {
            const float xs0[8] = {xa0.x, xa0.y, xa0.z, xa0.w, xa1.x, xa1.y, xa1.z, xa1.w};
            const float xs1[8] = {xb0.x, xb0.y, xb0.z, xb0.w, xb1.x, xb1.y, xb1.z, xb1.w};
#pragma unroll
            for (int q = 0; q < 4; q++) { xacc0[q] = bias[q]; xacc1[q] = bias[q]; }
#pragma unroll
            for (int k = 0; k < INSZ; k++)
#pragma unroll
                for (int q = 0; q < 4; q++) {
                    xacc0[q] = fmaf(xs0[k], wx[k][q], xacc0[q]);
                    xacc1[q] = fmaf(xs1[k], wx[k][q], xacc1[q]);
                }
        }

        // ---- state update ----
        c0 = ff0 * c0 + ii0 * gg0;
        c1 = ff1 * c1 + ii1 * gg1;
        h0 = oo0 * tanh_hw(c0);
        h1 = oo1 * tanh_hw(c1);

        if (t + 1 < T_STEPS) {
            if (active) {
                sv[nxt][g][j]          = h0;
                sv[nxt][g + GROUPS][j] = h1;
            }
            __syncthreads();
        }
        cur = nxt;
    }

    if (ok0) out[b0 * HID + j] = h0;
    if (ok1) out[b1 * HID + j] = h1;
}

extern "C" void kernel_launch(void* const* d_in, const int* in_sizes, int n_in,
                              void* d_out, int out_size) {
    const float* x   = (const float*)d_in[0];
    const float* Wih = (const float*)d_in[1];
    const float* bih = (const float*)d_in[2];
    const float* Whh = (const float*)d_in[3];
    const float* bhh = (const float*)d_in[4];
    const float* hx0 = (const float*)d_in[5];
    const float* cx0 = (const float*)d_in[6];
    float* out = (float*)d_out;

    const int grid = (BATCH + NGE - 1) / NGE;  // 683
    lstm_kernel<<<grid, NTHREADS>>>(x, Wih, bih, Whh, bhh, hx0, cx0, out);
}

// round 15
// speedup vs baseline: 1.3732x; 1.0996x over previous
#include <cuda_runtime.h>
#include <cuda_fp16.h>

#define T_STEPS  2048
#define BATCH    4096
#define INSZ     8
#define HID      20
#define G4       80
#define GROUPS   3       // thread groups per CTA
#define NGE      6       // batch elems per CTA (2 per thread group)
#define NTHREADS 64      // 2 warps; 60 active lanes
#define ROWH     24      // padded smem row (half2): h[0:20] pairs, pad (96 B)

// hardware tanh: 1 MUFU op
__device__ __forceinline__ float tanh_hw(float v) {
    float r;
    asm("tanh.approx.f32 %0, %1;" : "=f"(r) : "f"(v));
    return r;
}
__device__ __forceinline__ float sigmoid_hw(float v) {
    return fmaf(tanh_hw(0.5f * v), 0.5f, 0.5f);
}

__global__ void __launch_bounds__(NTHREADS)
lstm_kernel(const float* __restrict__ x,    // [T, B, 8]
            const float* __restrict__ Wih,  // [8, 80]
            const float* __restrict__ bih,  // [80]
            const float* __restrict__ Whh,  // [20, 80]
            const float* __restrict__ bhh,  // [80]
            const float* __restrict__ hx0,  // [1, 20]
            const float* __restrict__ cx0,  // [1, 20]
            float* __restrict__ out)        // [B, 20]
{
    // each entry: half2 = (h_elem0, h_elem1)
    __shared__ __align__(16) __half2 sv[2][GROUPS][ROWH];

    const int tid = threadIdx.x;
    const bool active = (tid < GROUPS * HID);   // 60 of 64
    const int tc  = active ? tid : 0;
    const int g   = tc / HID;             // 0..2
    const int j   = tc % HID;             // 0..19
    const int b0  = blockIdx.x * NGE + g;
    const int b1  = b0 + GROUPS;
    const bool ok0 = active && (b0 < BATCH);
    const bool ok1 = active && (b1 < BATCH);
    const int cb0 = (b0 < BATCH) ? b0 : 0;
    const int cb1 = (b1 < BATCH) ? b1 : 0;

    // ---- recurrent weights as duplicated half2 (80 regs) ----
    __half2 wh2[HID][4];
#pragma unroll
    for (int k = 0; k < HID; k++)
#pragma unroll
        for (int q = 0; q < 4; q++)
            wh2[k][q] = __half2half2(__float2half_rn(__ldg(&Whh[k * G4 + q * HID + j])));

    // ---- input weights fp32 (32 regs) ----
    float wx[INSZ][4];
#pragma unroll
    for (int k = 0; k < INSZ; k++)
#pragma unroll
        for (int q = 0; q < 4; q++)
            wx[k][q] = __ldg(&Wih[k * G4 + q * HID + j]);

    float bias[4];
#pragma unroll
    for (int q = 0; q < 4; q++)
        bias[q] = __ldg(&bih[q * HID + j]) + __ldg(&bhh[q * HID + j]);

    float h0 = hx0[j], c0 = cx0[j];
    float h1 = h0,     c1 = c0;

    const float4* x4 = reinterpret_cast<const float4*>(x);

    // ---- prologue: xacc = bias + x_0 * W_ih (fp32, exact) ----
    float xacc0[4], xacc1[4];
    {
        const float4 a0 = x4[(0 * BATCH + cb0) * 2 + 0];
        const float4 a1 = x4[(0 * BATCH + cb0) * 2 + 1];
        const float4 e0 = x4[(0 * BATCH + cb1) * 2 + 0];
        const float4 e1 = x4[(0 * BATCH + cb1) * 2 + 1];
        const float xs0[8] = {a0.x, a0.y, a0.z, a0.w, a1.x, a1.y, a1.z, a1.w};
        const float xs1[8] = {e0.x, e0.y, e0.z, e0.w, e1.x, e1.y, e1.z, e1.w};
#pragma unroll
        for (int q = 0; q < 4; q++) { xacc0[q] = bias[q]; xacc1[q] = bias[q]; }
#pragma unroll
        for (int k = 0; k < INSZ; k++)
#pragma unroll
            for (int q = 0; q < 4; q++) {
                xacc0[q] = fmaf(xs0[k], wx[k][q], xacc0[q]);
                xacc1[q] = fmaf(xs1[k], wx[k][q], xacc1[q]);
            }
    }

    if (active)
        sv[0][g][j] = __floats2half2_rn(h0, h1);
    __syncthreads();

    int cur = 0;
#pragma unroll 2
    for (int t = 0; t < T_STEPS; t++) {
        const int nxt = cur ^ 1;

        // ---- x loads for step t+1 (latency hidden by HFMA2 block) ----
        const int tn = (t + 1 < T_STEPS) ? (t + 1) : t;
        const float4 xa0 = x4[((size_t)tn * BATCH + cb0) * 2 + 0];
        const float4 xa1 = x4[((size_t)tn * BATCH + cb0) * 2 + 1];
        const float4 xb0 = x4[((size_t)tn * BATCH + cb1) * 2 + 0];
        const float4 xb1 = x4[((size_t)tn * BATCH + cb1) * 2 + 1];

        // ---- packed gate accumulation: 4 gates x 2 k-partials, half2 over (e0,e1) ----
        __half2 acc[4][2];
#pragma unroll
        for (int q = 0; q < 4; q++) {
            acc[q][0] = __float2half2_rn(0.0f);
            acc[q][1] = __float2half2_rn(0.0f);
        }
        const float4* r = reinterpret_cast<const float4*>(sv[cur][g]);  // 5 x float4 = 20 half2
#pragma unroll
        for (int kc = 0; kc < HID / 4; kc++) {
            const float4 blk = r[kc];
            __half2 hp[4];
            hp[0] = *reinterpret_cast<const __half2*>(&blk.x);
            hp[1] = *reinterpret_cast<const __half2*>(&blk.y);
            hp[2] = *reinterpret_cast<const __half2*>(&blk.z);
            hp[3] = *reinterpret_cast<const __half2*>(&blk.w);
            const int k = kc * 4;
#pragma unroll
            for (int s = 0; s < 4; s++)
#pragma unroll
                for (int q = 0; q < 4; q++)
                    acc[q][s & 1] = __hfma2(hp[s], wh2[k + s][q], acc[q][s & 1]);
        }

        // ---- combine partials, unpack to fp32, add x-part ----
        float a0f[4], a1f[4];
#pragma unroll
        for (int q = 0; q < 4; q++) {
            const __half2 s = __hadd2(acc[q][0], acc[q][1]);
            const float2 f = __half22float2(s);
            a0f[q] = xacc0[q] + f.x;
            a1f[q] = xacc1[q] + f.y;
        }

        // ---- activations (1 MUFU each) ----
        const float ii0 = sigmoid_hw(a0f[0]);
        const float ff0 = sigmoid_hw(a0f[1]);
        const float gg0 = tanh_hw(a0f[2]);
        const float oo0 = sigmoid_hw(a0f[3]);
        const float ii1 = sigmoid_hw(a1f[0]);
        const float ff1 = sigmoid_hw(a1f[1]);
        const float gg1 = tanh_hw(a1f[2]);
        const float oo1 = sigmoid_hw(a1f[3]);

        // ---- next step's x-projection (fp32, fills MUFU shadow) ----
        {
            const float xs0[8] = {xa0.x, xa0.y, xa0.z, xa0.w, xa1.x, xa1.y, xa1.z, xa1.w};
            const float xs1[8] = {xb0.x, xb0.y, xb0.z, xb0.w, xb1.x, xb1.y, xb1.z, xb1.w};
#pragma unroll
            for (int q = 0; q < 4; q++) { xacc0[q] = bias[q]; xacc1[q] = bias[q]; }
#pragma unroll
            for (int k = 0; k < INSZ; k++)
#pragma unroll
                for (int q = 0; q < 4; q++) {
                    xacc0[q] = fmaf(xs0[k], wx[k][q], xacc0[q]);
                    xacc1[q] = fmaf(xs1[k], wx[k][q], xacc1[q]);
                }
        }

        // ---- state update (fp32 c) ----
        c0 = ff0 * c0 + ii0 * gg0;
        c1 = ff1 * c1 + ii1 * gg1;
        h0 = oo0 * tanh_hw(c0);
        h1 = oo1 * tanh_hw(c1);

        if (t + 1 < T_STEPS) {
            if (active)
                sv[nxt][g][j] = __floats2half2_rn(h0, h1);  // 1 cvt + 1 STS.32
            __syncthreads();
        }
        cur = nxt;
    }

    if (ok0) out[b0 * HID + j] = h0;
    if (ok1) out[b1 * HID + j] = h1;
}

extern "C" void kernel_launch(void* const* d_in, const int* in_sizes, int n_in,
                              void* d_out, int out_size) {
    const float* x   = (const float*)d_in[0];
    const float* Wih = (const float*)d_in[1];
    const float* bih = (const float*)d_in[2];
    const float* Whh = (const float*)d_in[3];
    const float* bhh = (const float*)d_in[4];
    const float* hx0 = (const float*)d_in[5];
    const float* cx0 = (const float*)d_in[6];
    float* out = (float*)d_out;

    const int grid = (BATCH + NGE - 1) / NGE;  // 683
    lstm_kernel<<<grid, NTHREADS>>>(x, Wih, bih, Whh, bhh, hx0, cx0, out);
}